// round 2
// baseline (speedup 1.0000x reference)
#include <cuda_runtime.h>
#include <math.h>

#define B_  4
#define L_  256
#define D_  256
#define P_  32
#define H_  8
#define HD_ 32
#define DH_ 128   // D/2

typedef unsigned long long u64;

// ---- packed f32x2 helpers (sm_100a) ----
__device__ __forceinline__ u64 pk2(float lo, float hi) {
    u64 r;
    asm("mov.b64 %0, {%1, %2};" : "=l"(r) : "r"(__float_as_uint(lo)), "r"(__float_as_uint(hi)));
    return r;
}
__device__ __forceinline__ void upk2(u64 v, float& lo, float& hi) {
    unsigned a, b;
    asm("mov.b64 {%0, %1}, %2;" : "=r"(a), "=r"(b) : "l"(v));
    lo = __uint_as_float(a); hi = __uint_as_float(b);
}
__device__ __forceinline__ void fma2(u64& d, u64 a, u64 b) {
    asm("fma.rn.f32x2 %0, %1, %2, %0;" : "+l"(d) : "l"(a), "l"(b));
}
__device__ __forceinline__ u64 mul2(u64 a, u64 b) {
    u64 d;
    asm("mul.rn.f32x2 %0, %1, %2;" : "=l"(d) : "l"(a), "l"(b));
    return d;
}

// ---- scratch (static device arrays; no allocation) ----
__device__ float g_k[B_*L_*D_];
__device__ float g_v[B_*L_*D_];
__device__ float g_q[B_*P_*L_*D_];
__device__ float g_ctx[B_*P_*L_*D_];
__device__ float g_W2q[DH_*D_];
__device__ float g_bq2[D_];

// ---------------------------------------------------------------------------
// Kernel 1: fuse W2q = w2 @ wq  (128x256), bq2 = b2 @ wq + bq
// ---------------------------------------------------------------------------
__global__ void fuse_w_kernel(const float* __restrict__ w2, const float* __restrict__ wq,
                              const float* __restrict__ b2, const float* __restrict__ bq) {
    int j = blockIdx.x, c = threadIdx.x;
    float acc = 0.f;
    for (int k = 0; k < D_; k++) acc = fmaf(w2[j*D_+k], wq[k*D_+c], acc);
    g_W2q[j*D_+c] = acc;
    if (j == 0) {
        float a = 0.f;
        for (int k = 0; k < D_; k++) a = fmaf(b2[k], wq[k*D_+c], a);
        g_bq2[c] = a + bq[c];
    }
}

// ---------------------------------------------------------------------------
// Kernel 2: k = ehr@wk + bk, v = ehr@wv + bv   (1024 rows)
// ---------------------------------------------------------------------------
__global__ void kv_kernel(const float* __restrict__ ehr,
                          const float* __restrict__ wk, const float* __restrict__ bk,
                          const float* __restrict__ wv, const float* __restrict__ bv) {
    __shared__ float sx[8*D_];
    int row0 = blockIdx.x * 8;
    int tid = threadIdx.x;
    for (int i = tid; i < 8*D_; i += 256) sx[i] = ehr[row0*D_ + i];
    __syncthreads();
    int c = tid;
    float ak[8], av[8];
    float bkc = bk[c], bvc = bv[c];
#pragma unroll
    for (int r = 0; r < 8; r++) { ak[r] = bkc; av[r] = bvc; }
    for (int d = 0; d < D_; d++) {
        float wkd = wk[d*D_+c];
        float wvd = wv[d*D_+c];
#pragma unroll
        for (int r = 0; r < 8; r++) {
            float x = sx[r*D_+d];
            ak[r] = fmaf(x, wkd, ak[r]);
            av[r] = fmaf(x, wvd, av[r]);
        }
    }
#pragma unroll
    for (int r = 0; r < 8; r++) {
        g_k[(row0+r)*D_+c] = ak[r];
        g_v[(row0+r)*D_+c] = av[r];
    }
}

// ---------------------------------------------------------------------------
// Kernel 3: tf -> gelu MLP -> q = scale*(h@W2q + bq2)
// grid 1024 (32 rows/block), block 256. Per thread: 8 rows x 4 cols (f32x2).
// ---------------------------------------------------------------------------
__global__ void q_kernel(const float* __restrict__ ehr_times, const float* __restrict__ itv,
                         const float* __restrict__ w1, const float* __restrict__ b1) {
    __shared__ float sh[32*DH_];
    __shared__ float3 stf[32];
    int tid = threadIdx.x;
    int g0 = blockIdx.x * 32;
    int b  = g0 / (P_*L_);
    int p  = (g0 / L_) % P_;
    int l0 = g0 % L_;
    if (tid < 32) {
        float t = ehr_times[b*L_ + l0 + tid];
        float s = itv[(b*P_+p)*2 + 0];
        float e = itv[(b*P_+p)*2 + 1];
        float ds = t - s, de = e - t;
        float x  = ds * de;
        float sg = 1.f / (1.f + expf(-x));
        stf[tid] = make_float3(ds, de, sg);
    }
    __syncthreads();
    for (int i = tid; i < 32*DH_; i += 256) {
        int r = i >> 7, j = i & 127;
        float3 tf = stf[r];
        float z = tf.x*w1[j] + tf.y*w1[DH_+j] + tf.z*w1[2*DH_+j] + b1[j];
        sh[i] = 0.5f * z * (1.f + erff(z * 0.70710678118654752f));   // exact gelu
    }
    __syncthreads();
    int c4 = (tid & 63) * 4;
    int rg = (tid >> 6) * 8;
    u64 acc[8][2];
    {
        ulonglong2 bias = *(const ulonglong2*)&g_bq2[c4];
#pragma unroll
        for (int r = 0; r < 8; r++) { acc[r][0] = bias.x; acc[r][1] = bias.y; }
    }
    for (int j = 0; j < DH_; j++) {
        ulonglong2 w = *(const ulonglong2*)&g_W2q[j*D_ + c4];
#pragma unroll
        for (int r = 0; r < 8; r++) {
            float x = sh[(rg+r)*DH_ + j];
            u64 x2 = pk2(x, x);
            fma2(acc[r][0], x2, w.x);
            fma2(acc[r][1], x2, w.y);
        }
    }
    const float scale = 0.17677669529663687f;   // 32^-0.5
    u64 s2 = pk2(scale, scale);
#pragma unroll
    for (int r = 0; r < 8; r++) {
        ulonglong2 o;
        o.x = mul2(acc[r][0], s2);
        o.y = mul2(acc[r][1], s2);
        *(ulonglong2*)&g_q[(g0+rg+r)*D_ + c4] = o;
    }
}

// ---------------------------------------------------------------------------
// Kernel 4: attention per (b,p,h). One thread = one query row, online softmax.
// Packed f32x2 along HD. grid (H,P,B), block 256.
// ---------------------------------------------------------------------------
__global__ void attn_kernel(const float* __restrict__ ehr_times, const float* __restrict__ itv) {
    extern __shared__ float smem[];
    float* sk = smem;
    float* sv = smem + L_*HD_;
    float* sb = smem + 2*L_*HD_;
    int h = blockIdx.x, p = blockIdx.y, b = blockIdx.z;
    int tid = threadIdx.x;

    // load K,V head slices as float4
    const float4* gk4 = (const float4*)g_k;
    const float4* gv4 = (const float4*)g_v;
    float4* sk4w = (float4*)sk;
    float4* sv4w = (float4*)sv;
    for (int i = tid; i < L_*8; i += 256) {
        int j = i >> 3, f = i & 7;
        int src = (b*L_+j)*(D_/4) + h*8 + f;
        sk4w[i] = gk4[src];
        sv4w[i] = gv4[src];
    }
    {
        float s = itv[(b*P_+p)*2 + 0];
        float e = itv[(b*P_+p)*2 + 1];
        float ctr = 0.5f*(s+e);
        float t = ehr_times[b*L_ + tid];
        sb[tid] = (t >= s && t <= e) ? -fabsf(t - ctr) : -1e30f;
    }
    __syncthreads();

    int l = tid;
    // q row: 16 packed pairs
    u64 q2[16];
    {
        const ulonglong2* gq2 = (const ulonglong2*)&g_q[((b*P_+p)*L_ + l)*D_ + h*HD_];
#pragma unroll
        for (int i = 0; i < 8; i++) {
            ulonglong2 t = gq2[i];
            q2[2*i] = t.x; q2[2*i+1] = t.y;
        }
    }

    float m = -1e30f, den = 0.f;
    u64 acc[16];
#pragma unroll
    for (int i = 0; i < 16; i++) acc[i] = 0ull;

    const ulonglong2* sk2 = (const ulonglong2*)sk;
    const ulonglong2* sv2 = (const ulonglong2*)sv;
    for (int j = 0; j < L_; j++) {
        // ---- score: 4 independent packed chains of 4 ----
        u64 c0 = 0ull, c1 = 0ull, c2 = 0ull, c3 = 0ull;
#pragma unroll
        for (int i = 0; i < 4; i++) {
            ulonglong2 ka = sk2[j*8 + 2*i];
            ulonglong2 kb = sk2[j*8 + 2*i + 1];
            fma2(c0, q2[4*i+0], ka.x);
            fma2(c1, q2[4*i+1], ka.y);
            fma2(c2, q2[4*i+2], kb.x);
            fma2(c3, q2[4*i+3], kb.y);
        }
        float lo0, hi0, lo1, hi1;
        upk2(c0, lo0, hi0); upk2(c1, lo1, hi1);
        float sA = (lo0 + hi0) + (lo1 + hi1);
        upk2(c2, lo0, hi0); upk2(c3, lo1, hi1);
        float s = sA + (lo0 + hi0) + (lo1 + hi1) + sb[j];

        if (s > m) {
            float corr = __expf(m - s);
            den *= corr;
            u64 corr2 = pk2(corr, corr);
#pragma unroll
            for (int i = 0; i < 16; i++) acc[i] = mul2(acc[i], corr2);
            m = s;
        }
        float pv = __expf(s - m);
        den += pv;
        u64 pv2 = pk2(pv, pv);
#pragma unroll
        for (int i = 0; i < 8; i++) {
            ulonglong2 vv = sv2[j*8 + i];
            fma2(acc[2*i],   pv2, vv.x);
            fma2(acc[2*i+1], pv2, vv.y);
        }
    }
    float inv = 1.f / den;
    u64 inv2 = pk2(inv, inv);
    ulonglong2* go = (ulonglong2*)&g_ctx[((b*P_+p)*L_ + l)*D_ + h*HD_];
#pragma unroll
    for (int i = 0; i < 8; i++) {
        ulonglong2 o;
        o.x = mul2(acc[2*i],   inv2);
        o.y = mul2(acc[2*i+1], inv2);
        go[i] = o;
    }
}

// ---------------------------------------------------------------------------
// Kernel 5: out = ctx @ wo + bo   (32768 x 256 x 256), packed over columns
// ---------------------------------------------------------------------------
__global__ void out_kernel(const float* __restrict__ wo, const float* __restrict__ bo,
                           float* __restrict__ out) {
    __shared__ float sx[32*D_];
    int tid = threadIdx.x;
    int row0 = blockIdx.x * 32;
    for (int i = tid; i < 32*D_; i += 256) sx[i] = g_ctx[row0*D_ + i];
    __syncthreads();
    int c4 = (tid & 63) * 4;
    int rg = (tid >> 6) * 8;
    u64 acc[8][2];
    {
        ulonglong2 bias = *(const ulonglong2*)&bo[c4];
#pragma unroll
        for (int r = 0; r < 8; r++) { acc[r][0] = bias.x; acc[r][1] = bias.y; }
    }
    for (int k = 0; k < D_; k++) {
        ulonglong2 w = *(const ulonglong2*)&wo[k*D_ + c4];
#pragma unroll
        for (int r = 0; r < 8; r++) {
            float x = sx[(rg+r)*D_ + k];
            u64 x2 = pk2(x, x);
            fma2(acc[r][0], x2, w.x);
            fma2(acc[r][1], x2, w.y);
        }
    }
#pragma unroll
    for (int r = 0; r < 8; r++) {
        ulonglong2 o; o.x = acc[r][0]; o.y = acc[r][1];
        *(ulonglong2*)&out[(row0+rg+r)*D_ + c4] = o;
    }
}

// ---------------------------------------------------------------------------
extern "C" void kernel_launch(void* const* d_in, const int* in_sizes, int n_in,
                              void* d_out, int out_size) {
    const float* ehr       = (const float*)d_in[0];
    const float* ehr_times = (const float*)d_in[1];
    const float* itv       = (const float*)d_in[2];
    const float* w1        = (const float*)d_in[3];
    const float* b1        = (const float*)d_in[4];
    const float* w2        = (const float*)d_in[5];
    const float* b2        = (const float*)d_in[6];
    const float* wq        = (const float*)d_in[7];
    const float* bq        = (const float*)d_in[8];
    const float* wk        = (const float*)d_in[9];
    const float* bk        = (const float*)d_in[10];
    const float* wv        = (const float*)d_in[11];
    const float* bv        = (const float*)d_in[12];
    const float* wo        = (const float*)d_in[13];
    const float* bo        = (const float*)d_in[14];
    float* out = (float*)d_out;

    fuse_w_kernel<<<DH_, D_>>>(w2, wq, b2, bq);
    kv_kernel<<<B_*L_/8, 256>>>(ehr, wk, bk, wv, bv);
    q_kernel<<<B_*P_*L_/32, 256>>>(ehr_times, itv, w1, b1);

    int attn_smem = (2*L_*HD_ + L_) * (int)sizeof(float);   // 66560 B
    cudaFuncSetAttribute(attn_kernel, cudaFuncAttributeMaxDynamicSharedMemorySize, attn_smem);
    attn_kernel<<<dim3(H_, P_, B_), 256, attn_smem>>>(ehr_times, itv);

    out_kernel<<<B_*P_*L_/32, 256>>>(wo, bo, out);
}